// round 6
// baseline (speedup 1.0000x reference)
#include <cuda_runtime.h>
#include <math.h>

// Problem constants (fixed by the reference setup)
#define N_USER 60000
#define N_ITEM 40000
#define NN     (N_USER + N_ITEM)   // 100000 nodes
#define D      64
#define EMAX   800000
#define EHALF  (EMAX / 2)
#define NB_SCAN ((NN + 1023) / 1024)   // 98 blocks

// ---- static device scratch (no allocations allowed) ----
__device__ float  g_embA[NN * D];
__device__ float  g_embB[NN * D];
__device__ float  g_light[NN * D];
__device__ float  g_rnorm[NN];    // reciprocal norms
__device__ float  g_rowsum[NN];   // reciprocal L1 rowsums (1 if rowsum<=0)
__device__ float4 g_edge[EMAX];   // {col(bits), cos, mem, aval}
__device__ int2   g_cr[EHALF];    // user-side CSR slots: {col, reverse slot}
__device__ int    g_rowptr[NN + 1];
__device__ int    g_deg[NN];
__device__ int    g_bsum[128];

// ---------------- CSR build ----------------

__global__ void k_hist(const int* __restrict__ src, int E) {
    for (int e = blockIdx.x * blockDim.x + threadIdx.x; e < E;
         e += gridDim.x * blockDim.x)
        atomicAdd(&g_deg[src[e]], 1);
}

__global__ void k_scanA() {
    __shared__ int wsum[32];
    int i = blockIdx.x * 1024 + threadIdx.x;
    int lane = threadIdx.x & 31, wid = threadIdx.x >> 5;
    int v = (i < NN) ? g_deg[i] : 0;
    int x = v;
    #pragma unroll
    for (int o = 1; o < 32; o <<= 1) {
        int y = __shfl_up_sync(0xffffffffu, x, o);
        if (lane >= o) x += y;
    }
    if (lane == 31) wsum[wid] = x;
    __syncthreads();
    if (wid == 0) {
        int s = wsum[lane];
        #pragma unroll
        for (int o = 1; o < 32; o <<= 1) {
            int y = __shfl_up_sync(0xffffffffu, s, o);
            if (lane >= o) s += y;
        }
        wsum[lane] = s;
    }
    __syncthreads();
    int woff = (wid > 0) ? wsum[wid - 1] : 0;
    int incl = x + woff;
    if (i < NN) g_rowptr[i] = incl - v;  // exclusive, local to block
    if (threadIdx.x == 1023) g_bsum[blockIdx.x] = incl;
}

__global__ void k_scanB(int nb) {
    int i = threadIdx.x;
    int v = (i < nb) ? g_bsum[i] : 0;
    int x = v;
    #pragma unroll
    for (int o = 1; o < 32; o <<= 1) {
        int y = __shfl_up_sync(0xffffffffu, x, o);
        if ((i & 31) >= o) x += y;
    }
    __shared__ int ws[4];
    if ((i & 31) == 31) ws[i >> 5] = x;
    __syncthreads();
    int off = 0;
    for (int w = 0; w < (i >> 5); w++) off += ws[w];
    if (i < nb) g_bsum[i] = x - v + off;  // exclusive
}

__global__ void k_scanC(int E) {
    int i = blockIdx.x * 1024 + threadIdx.x;
    if (i < NN) {
        g_rowptr[i] += g_bsum[blockIdx.x];
        g_deg[i] = 0;  // reset as scatter cursor
    }
    if (i == 0) g_rowptr[NN] = E;
}

// scatter BOTH directions of each undirected edge; record reverse-slot mapping.
__global__ void k_scatter(const int* __restrict__ src, const float* __restrict__ adj,
                          int EH) {
    for (int e = blockIdx.x * blockDim.x + threadIdx.x; e < EH;
         e += gridDim.x * blockDim.x) {
        int u = src[e];
        int i = src[e + EH];
        float a = adj[e];
        int pos1 = g_rowptr[u] + atomicAdd(&g_deg[u], 1);
        int pos2 = g_rowptr[i] + atomicAdd(&g_deg[i], 1);
        g_edge[pos1] = make_float4(__int_as_float(i), 0.f, a, a);
        g_edge[pos2] = make_float4(__int_as_float(u), 0.f, a, a);
        g_cr[pos1]   = make_int2(i, pos2);   // user rows occupy slots [0, EH)
    }
}

// ---------------- init embeddings + light + layer-0 rnorm (fused) ----------------

__global__ void k_init(const float* __restrict__ ue, const float* __restrict__ ie) {
    int row = blockIdx.x * (blockDim.x >> 5) + (threadIdx.x >> 5);
    if (row >= NN) return;
    int lane = threadIdx.x & 31;
    const float* srcp = (row < N_USER) ? (ue + row * D) : (ie + (row - N_USER) * D);
    float2 v = *(const float2*)(srcp + lane * 2);
    *(float2*)(g_embA + row * D + lane * 2)  = v;
    *(float2*)(g_light + row * D + lane * 2) = v;
    float s = v.x * v.x + v.y * v.y;
    #pragma unroll
    for (int o = 16; o; o >>= 1) s += __shfl_xor_sync(0xffffffffu, s, o);
    if (lane == 0) g_rnorm[row] = (s > 1e-24f) ? rsqrtf(s) : 0.f;
}

// ---------------- per-layer edge passes ----------------
// k_cos: USER rows only (cos symmetric; scatter to reverse slot too).
// Warp per row; 4 edge-groups of 8 lanes; 8 dims/lane; 2-stage software pipeline:
// records prefetched 2 iters ahead, emb/rnorm gathers 1 iter ahead.

__global__ __launch_bounds__(256) void k_cos(int cur) {
    const float* __restrict__ emb = cur ? g_embB : g_embA;
    int row = blockIdx.x * 8 + (threadIdx.x >> 5);
    if (row >= N_USER) return;
    int lane = threadIdx.x & 31;
    int g = lane >> 3, sl = lane & 7;

    const float* rp = emb + row * D + sl * 8;
    float4 e0 = *(const float4*)(rp);
    float4 e1 = *(const float4*)(rp + 4);
    float rn_r = g_rnorm[row];

    int beg = g_rowptr[row], end = g_rowptr[row + 1];
    int nit = (end - beg + 3) >> 2;

    // pipeline prologue: stage0 gather in flight, stage1 record in flight
    int pos0 = beg + g;
    bool act0 = pos0 < end;
    int2 cr0 = act0 ? g_cr[pos0] : make_int2(0, 0);
    float4 d00 = make_float4(0, 0, 0, 0), d01 = make_float4(0, 0, 0, 0);
    float rn0 = 0.f;
    if (act0) {
        const float* cp = emb + cr0.x * D + sl * 8;
        d00 = *(const float4*)(cp);
        d01 = *(const float4*)(cp + 4);
        rn0 = g_rnorm[cr0.x];
    }
    int pos1 = pos0 + 4;
    bool act1 = pos1 < end;
    int2 cr1 = act1 ? g_cr[pos1] : make_int2(0, 0);

    float rs = 0.f;
    for (int it = 0; it < nit; it++) {
        // issue stage-1 gathers (independent of stage-0 consume)
        float4 d10 = make_float4(0, 0, 0, 0), d11 = make_float4(0, 0, 0, 0);
        float rn1 = 0.f;
        if (act1) {
            const float* cp = emb + cr1.x * D + sl * 8;
            d10 = *(const float4*)(cp);
            d11 = *(const float4*)(cp + 4);
            rn1 = g_rnorm[cr1.x];
        }
        // prefetch stage-2 record
        int pos2 = pos1 + 4;
        bool act2 = pos2 < end;
        int2 cr2 = act2 ? g_cr[pos2] : make_int2(0, 0);

        // consume stage 0
        float p = 0.f;
        if (act0)
            p = e0.x * d00.x + e0.y * d00.y + e0.z * d00.z + e0.w * d00.w
              + e1.x * d01.x + e1.y * d01.y + e1.z * d01.z + e1.w * d01.w;
        p += __shfl_xor_sync(0xffffffffu, p, 1);
        p += __shfl_xor_sync(0xffffffffu, p, 2);
        p += __shfl_xor_sync(0xffffffffu, p, 4);
        float cs = p * rn_r * rn0;          // 0 for inactive (rn0 = 0)
        if (act0 && sl == 0) {
            ((float*)(g_edge + pos0))[1] = cs;   // user-side slot
            ((float*)(g_edge + cr0.y))[1] = cs;  // item-side (reverse) slot
        }
        rs += fabsf(cs);

        // rotate pipeline
        pos0 = pos1; act0 = act1; cr0 = cr1; d00 = d10; d01 = d11; rn0 = rn1;
        pos1 = pos2; act1 = act2; cr1 = cr2;
    }
    rs += __shfl_xor_sync(0xffffffffu, rs, 8);
    rs += __shfl_xor_sync(0xffffffffu, rs, 16);
    if (lane == 0) g_rowsum[row] = (rs > 0.f) ? 1.f / rs : 1.f;
}

// item-row reciprocal L1 rowsums from the already-written cos values (scalar reads)
__global__ __launch_bounds__(256) void k_rowsum_it() {
    int row = N_USER + blockIdx.x * 8 + (threadIdx.x >> 5);
    if (row >= NN) return;
    int lane = threadIdx.x & 31;
    int beg = g_rowptr[row], end = g_rowptr[row + 1];
    float rs = 0.f;
    for (int pos = beg + lane; pos < end; pos += 32)
        rs += fabsf(((const float*)(g_edge + pos))[1]);
    #pragma unroll
    for (int o = 16; o; o >>= 1) rs += __shfl_xor_sync(0xffffffffu, rs, o);
    if (lane == 0) g_rowsum[row] = (rs > 0.f) ? 1.f / rs : 1.f;
}

// coef -> prune -> mem EMA -> SpMM row accumulate (+ light sum, + next rnorm)
// Same 2-stage pipeline as k_cos.
__global__ __launch_bounds__(256) void k_spmm(int cur, int last,
                                              const float* __restrict__ W,
                                              const float* __restrict__ B) {
    const float* __restrict__ embin = cur ? g_embB : g_embA;
    float* embout                   = cur ? g_embA : g_embB;
    int row = blockIdx.x * 8 + (threadIdx.x >> 5);
    if (row >= NN) return;
    int lane = threadIdx.x & 31;
    int g = lane >> 3, sl = lane & 7;

    float w0 = W[0], w1 = W[1], bb = B[0];
    float invr = g_rowsum[row];   // already reciprocal
    int beg = g_rowptr[row], end = g_rowptr[row + 1];
    int nit = (end - beg + 3) >> 2;

    // pipeline prologue
    int pos0 = beg + g;
    bool act0 = pos0 < end;
    float4 er0 = act0 ? g_edge[pos0] : make_float4(0, 0, 0, 0);
    float4 d00 = make_float4(0, 0, 0, 0), d01 = make_float4(0, 0, 0, 0);
    float rsc0 = 0.f;
    if (act0) {
        int c = __float_as_int(er0.x);
        const float* cp = embin + c * D + sl * 8;
        d00 = *(const float4*)(cp);
        d01 = *(const float4*)(cp + 4);
        rsc0 = g_rowsum[c];
    }
    int pos1 = pos0 + 4;
    bool act1 = pos1 < end;
    float4 er1 = act1 ? g_edge[pos1] : make_float4(0, 0, 0, 0);

    float a0 = 0.f, a1 = 0.f, a2 = 0.f, a3 = 0.f;
    float a4 = 0.f, a5 = 0.f, a6 = 0.f, a7 = 0.f;
    for (int it = 0; it < nit; it++) {
        // issue stage-1 gathers
        float4 d10 = make_float4(0, 0, 0, 0), d11 = make_float4(0, 0, 0, 0);
        float rsc1 = 0.f;
        if (act1) {
            int c = __float_as_int(er1.x);
            const float* cp = embin + c * D + sl * 8;
            d10 = *(const float4*)(cp);
            d11 = *(const float4*)(cp + 4);
            rsc1 = g_rowsum[c];
        }
        // prefetch stage-2 record
        int pos2 = pos1 + 4;
        bool act2 = pos2 < end;
        float4 er2 = act2 ? g_edge[pos2] : make_float4(0, 0, 0, 0);

        // consume stage 0
        if (act0) {
            float cs = er0.y;
            float c1 = cs * invr;
            float c2 = cs * rsc0;                  // cos symmetric: coef[rev] = cs / rowsum[dst]
            float z = w0 * c1 + w1 * c2 + bb;      // sigmoid(z)>0.5 <=> z>0
            float coef = (z > 0.f) ? c1 : 0.f;
            float m = 0.5f * (er0.z + coef);
            if (!last && sl == 0) ((float*)(g_edge + pos0))[2] = m;
            float gv = m * er0.w;
            a0 += gv * d00.x; a1 += gv * d00.y; a2 += gv * d00.z; a3 += gv * d00.w;
            a4 += gv * d01.x; a5 += gv * d01.y; a6 += gv * d01.z; a7 += gv * d01.w;
        }

        // rotate pipeline
        pos0 = pos1; act0 = act1; er0 = er1; d00 = d10; d01 = d11; rsc0 = rsc1;
        pos1 = pos2; act1 = act2; er1 = er2;
    }
    // combine the 4 groups (same dims live in lanes sl, sl+8, sl+16, sl+24)
    #pragma unroll
    for (int o = 8; o <= 16; o <<= 1) {
        a0 += __shfl_xor_sync(0xffffffffu, a0, o);
        a1 += __shfl_xor_sync(0xffffffffu, a1, o);
        a2 += __shfl_xor_sync(0xffffffffu, a2, o);
        a3 += __shfl_xor_sync(0xffffffffu, a3, o);
        a4 += __shfl_xor_sync(0xffffffffu, a4, o);
        a5 += __shfl_xor_sync(0xffffffffu, a5, o);
        a6 += __shfl_xor_sync(0xffffffffu, a6, o);
        a7 += __shfl_xor_sync(0xffffffffu, a7, o);
    }
    if (g == 0) {
        float* lp = g_light + row * D + sl * 8;
        float4 l0 = *(float4*)(lp);
        float4 l1 = *(float4*)(lp + 4);
        l0.x += a0; l0.y += a1; l0.z += a2; l0.w += a3;
        l1.x += a4; l1.y += a5; l1.z += a6; l1.w += a7;
        *(float4*)(lp)     = l0;
        *(float4*)(lp + 4) = l1;
    }
    if (!last) {
        float ss = a0 * a0 + a1 * a1 + a2 * a2 + a3 * a3
                 + a4 * a4 + a5 * a5 + a6 * a6 + a7 * a7;
        ss += __shfl_xor_sync(0xffffffffu, ss, 1);
        ss += __shfl_xor_sync(0xffffffffu, ss, 2);
        ss += __shfl_xor_sync(0xffffffffu, ss, 4);
        if (g == 0) {
            float* op = embout + row * D + sl * 8;
            *(float4*)(op)     = make_float4(a0, a1, a2, a3);
            *(float4*)(op + 4) = make_float4(a4, a5, a6, a7);
            if (sl == 0) g_rnorm[row] = (ss > 1e-24f) ? rsqrtf(ss) : 0.f;
        }
    }
}

// ---------------- final: fused gather + sigmoid GEMM ----------------

__global__ void k_gemm(const int* __restrict__ users, const int* __restrict__ items,
                       float* __restrict__ out, int Bu, int Bi) {
    __shared__ float As[64][65];
    __shared__ float Bs[64][65];
    int tx = threadIdx.x, ty = threadIdx.y;       // 16x16
    int t = ty * 16 + tx;
    int rowBase = blockIdx.y * 64, colBase = blockIdx.x * 64;
    #pragma unroll
    for (int i = 0; i < 4; i++) {
        int j = t + i * 256;       // float4 slot 0..1023
        int r = j >> 4;
        int kq = (j & 15) * 4;
        float4 a = make_float4(0, 0, 0, 0);
        if (rowBase + r < Bu) {
            int u = users[rowBase + r];
            float4 v = *(const float4*)(g_light + u * D + kq);
            a = make_float4(0.25f * v.x, 0.25f * v.y, 0.25f * v.z, 0.25f * v.w);
        }
        As[r][kq] = a.x; As[r][kq + 1] = a.y; As[r][kq + 2] = a.z; As[r][kq + 3] = a.w;
        float4 b = make_float4(0, 0, 0, 0);
        if (colBase + r < Bi) {
            int itm = items[colBase + r];
            float4 v = *(const float4*)(g_light + (N_USER + itm) * D + kq);
            b = make_float4(0.25f * v.x, 0.25f * v.y, 0.25f * v.z, 0.25f * v.w);
        }
        Bs[r][kq] = b.x; Bs[r][kq + 1] = b.y; Bs[r][kq + 2] = b.z; Bs[r][kq + 3] = b.w;
    }
    __syncthreads();
    float acc[4][4] = {};
    #pragma unroll
    for (int k = 0; k < 64; k++) {
        float a0 = As[ty * 4 + 0][k], a1 = As[ty * 4 + 1][k];
        float a2 = As[ty * 4 + 2][k], a3 = As[ty * 4 + 3][k];
        float b0 = Bs[tx * 4 + 0][k], b1 = Bs[tx * 4 + 1][k];
        float b2 = Bs[tx * 4 + 2][k], b3 = Bs[tx * 4 + 3][k];
        acc[0][0] += a0 * b0; acc[0][1] += a0 * b1; acc[0][2] += a0 * b2; acc[0][3] += a0 * b3;
        acc[1][0] += a1 * b0; acc[1][1] += a1 * b1; acc[1][2] += a1 * b2; acc[1][3] += a1 * b3;
        acc[2][0] += a2 * b0; acc[2][1] += a2 * b1; acc[2][2] += a2 * b2; acc[2][3] += a2 * b3;
        acc[3][0] += a3 * b0; acc[3][1] += a3 * b1; acc[3][2] += a3 * b2; acc[3][3] += a3 * b3;
    }
    #pragma unroll
    for (int i = 0; i < 4; i++)
        #pragma unroll
        for (int j = 0; j < 4; j++) {
            int r = rowBase + ty * 4 + i;
            int c = colBase + tx * 4 + j;
            if (r < Bu && c < Bi)
                out[r * Bi + c] = 1.f / (1.f + __expf(-acc[i][j]));
        }
}

// ---------------- launch ----------------

extern "C" void kernel_launch(void* const* d_in, const int* in_sizes, int n_in,
                              void* d_out, int out_size) {
    const int*   users    = (const int*)d_in[0];
    const int*   items    = (const int*)d_in[1];
    const float* user_emb = (const float*)d_in[2];
    const float* item_emb = (const float*)d_in[3];
    const float* W_prune  = (const float*)d_in[4];
    const float* b_prune  = (const float*)d_in[5];
    const int*   src      = (const int*)d_in[6];
    // d_in[7] = dst (mirrors src), d_in[8] = rev_perm (unused)
    const float* adj_vals = (const float*)d_in[9];

    int Bu = in_sizes[0];
    int Bi = in_sizes[1];
    int E  = in_sizes[6];
    int EH = E / 2;

    float* out = (float*)d_out;

    // zero degree counters
    void* degp = nullptr;
    cudaGetSymbolAddress(&degp, g_deg);
    cudaMemsetAsync(degp, 0, NN * sizeof(int));

    // CSR build
    k_hist<<<(E + 1023) / 1024, 1024>>>(src, E);
    k_scanA<<<NB_SCAN, 1024>>>();
    k_scanB<<<1, 128>>>(NB_SCAN);
    k_scanC<<<NB_SCAN, 1024>>>(E);
    k_scatter<<<(EH + 1023) / 1024, 1024>>>(src, adj_vals, EH);

    // init embeddings + light + layer-0 reciprocal norms
    k_init<<<(NN + 7) / 8, 256>>>(user_emb, item_emb);

    // 3 propagation layers
    int ublocks = (N_USER + 7) / 8;
    int iblocks = (N_ITEM + 7) / 8;
    int ablocks = (NN + 7) / 8;
    for (int l = 0; l < 3; l++) {
        int cur = l & 1;
        k_cos<<<ublocks, 256>>>(cur);
        k_rowsum_it<<<iblocks, 256>>>();
        k_spmm<<<ablocks, 256>>>(cur, l == 2, W_prune, b_prune);
    }

    // fused gather + sigmoid GEMM
    dim3 gblk(16, 16);
    dim3 ggrd((Bi + 63) / 64, (Bu + 63) / 64);
    k_gemm<<<ggrd, gblk>>>(users, items, out, Bu, Bi);
}

// round 7
// speedup vs baseline: 1.0695x; 1.0695x over previous
#include <cuda_runtime.h>
#include <math.h>

// Problem constants (fixed by the reference setup)
#define N_USER 60000
#define N_ITEM 40000
#define NN     (N_USER + N_ITEM)   // 100000 nodes
#define D      64
#define EMAX   800000
#define EHALF  (EMAX / 2)
#define NB_SCAN ((NN + 1023) / 1024)   // 98 blocks

// ---- static device scratch (no allocations allowed) ----
__device__ float  g_embA[NN * D];
__device__ float  g_embB[NN * D];
__device__ float  g_light[NN * D];
__device__ float  g_rnorm[NN];    // reciprocal norms
__device__ float  g_rowsum[NN];   // reciprocal L1 rowsums (1 if rowsum<=0)
__device__ float4 g_edge[EMAX];   // {col(bits), cos, mem, aval}
__device__ int2   g_cr[EHALF];    // user-side CSR slots: {col, reverse slot}
__device__ int    g_rowptr[NN + 1];
__device__ int    g_deg[NN];
__device__ int    g_bsum[128];

// ---------------- CSR build ----------------

__global__ void k_hist(const int* __restrict__ src, int E) {
    for (int e = blockIdx.x * blockDim.x + threadIdx.x; e < E;
         e += gridDim.x * blockDim.x)
        atomicAdd(&g_deg[src[e]], 1);
}

__global__ void k_scanA() {
    __shared__ int wsum[32];
    int i = blockIdx.x * 1024 + threadIdx.x;
    int lane = threadIdx.x & 31, wid = threadIdx.x >> 5;
    int v = (i < NN) ? g_deg[i] : 0;
    int x = v;
    #pragma unroll
    for (int o = 1; o < 32; o <<= 1) {
        int y = __shfl_up_sync(0xffffffffu, x, o);
        if (lane >= o) x += y;
    }
    if (lane == 31) wsum[wid] = x;
    __syncthreads();
    if (wid == 0) {
        int s = wsum[lane];
        #pragma unroll
        for (int o = 1; o < 32; o <<= 1) {
            int y = __shfl_up_sync(0xffffffffu, s, o);
            if (lane >= o) s += y;
        }
        wsum[lane] = s;
    }
    __syncthreads();
    int woff = (wid > 0) ? wsum[wid - 1] : 0;
    int incl = x + woff;
    if (i < NN) g_rowptr[i] = incl - v;  // exclusive, local to block
    if (threadIdx.x == 1023) g_bsum[blockIdx.x] = incl;
}

__global__ void k_scanB(int nb) {
    int i = threadIdx.x;
    int v = (i < nb) ? g_bsum[i] : 0;
    int x = v;
    #pragma unroll
    for (int o = 1; o < 32; o <<= 1) {
        int y = __shfl_up_sync(0xffffffffu, x, o);
        if ((i & 31) >= o) x += y;
    }
    __shared__ int ws[4];
    if ((i & 31) == 31) ws[i >> 5] = x;
    __syncthreads();
    int off = 0;
    for (int w = 0; w < (i >> 5); w++) off += ws[w];
    if (i < nb) g_bsum[i] = x - v + off;  // exclusive
}

__global__ void k_scanC(int E) {
    int i = blockIdx.x * 1024 + threadIdx.x;
    if (i < NN) {
        g_rowptr[i] += g_bsum[blockIdx.x];
        g_deg[i] = 0;  // reset as scatter cursor
    }
    if (i == 0) g_rowptr[NN] = E;
}

// scatter BOTH directions of each undirected edge; record reverse-slot mapping.
__global__ void k_scatter(const int* __restrict__ src, const float* __restrict__ adj,
                          int EH) {
    for (int e = blockIdx.x * blockDim.x + threadIdx.x; e < EH;
         e += gridDim.x * blockDim.x) {
        int u = src[e];
        int i = src[e + EH];
        float a = adj[e];
        int pos1 = g_rowptr[u] + atomicAdd(&g_deg[u], 1);
        int pos2 = g_rowptr[i] + atomicAdd(&g_deg[i], 1);
        g_edge[pos1] = make_float4(__int_as_float(i), 0.f, a, a);
        g_edge[pos2] = make_float4(__int_as_float(u), 0.f, a, a);
        g_cr[pos1]   = make_int2(i, pos2);   // user rows occupy slots [0, EH)
    }
}

// ---------------- init embeddings + light + layer-0 rnorm (fused) ----------------

__global__ void k_init(const float* __restrict__ ue, const float* __restrict__ ie) {
    int row = blockIdx.x * (blockDim.x >> 5) + (threadIdx.x >> 5);
    if (row >= NN) return;
    int lane = threadIdx.x & 31;
    const float* srcp = (row < N_USER) ? (ue + row * D) : (ie + (row - N_USER) * D);
    float2 v = *(const float2*)(srcp + lane * 2);
    *(float2*)(g_embA + row * D + lane * 2)  = v;
    *(float2*)(g_light + row * D + lane * 2) = v;
    float s = v.x * v.x + v.y * v.y;
    #pragma unroll
    for (int o = 16; o; o >>= 1) s += __shfl_xor_sync(0xffffffffu, s, o);
    if (lane == 0) g_rnorm[row] = (s > 1e-24f) ? rsqrtf(s) : 0.f;
}

// ---------------- per-layer edge passes ----------------
// k_cos: USER rows only (cos symmetric; scatter to reverse slot too).
// Warp per row; 4 edge-groups of 8 lanes.
// Lane sl covers dims [4sl, 4sl+4) and [32+4sl, 32+4sl+4): each LDG.128 covers
// exactly one 128B line of the row (halves L1tex wavefronts vs interleaved map).

__global__ __launch_bounds__(256) void k_cos(int cur) {
    const float* __restrict__ emb = cur ? g_embB : g_embA;
    int row = blockIdx.x * 8 + (threadIdx.x >> 5);
    if (row >= N_USER) return;
    int lane = threadIdx.x & 31;
    int g = lane >> 3, sl = lane & 7;

    const float* rp = emb + row * D + sl * 4;
    float4 e0 = *(const float4*)(rp);
    float4 e1 = *(const float4*)(rp + 32);
    float rn_r = g_rnorm[row];

    int beg = g_rowptr[row], end = g_rowptr[row + 1];
    int nit = (end - beg + 3) >> 2;

    // prefetch first {col, rev} for this group
    int pos = beg + g;
    bool actn = pos < end;
    int2 crn = actn ? g_cr[pos] : make_int2(0, 0);

    float rs = 0.f;
    for (int it = 0; it < nit; it++) {
        bool act = actn;
        int2 cr = crn;
        int curpos = pos;
        pos += 4;
        actn = pos < end;
        if (actn) crn = g_cr[pos];        // prefetch next iteration

        float p = 0.f;
        float rn_c = 0.f;
        if (act) {
            const float* cp = emb + cr.x * D + sl * 4;
            float4 d0 = *(const float4*)(cp);
            float4 d1 = *(const float4*)(cp + 32);
            rn_c = g_rnorm[cr.x];
            p = e0.x * d0.x + e0.y * d0.y + e0.z * d0.z + e0.w * d0.w
              + e1.x * d1.x + e1.y * d1.y + e1.z * d1.z + e1.w * d1.w;
        }
        p += __shfl_xor_sync(0xffffffffu, p, 1);
        p += __shfl_xor_sync(0xffffffffu, p, 2);
        p += __shfl_xor_sync(0xffffffffu, p, 4);
        float cs = p * rn_r * rn_c;        // 0 for inactive (rn_c = 0)
        if (act && sl == 0) {
            ((float*)(g_edge + curpos))[1] = cs;   // user-side slot
            ((float*)(g_edge + cr.y))[1]   = cs;   // item-side (reverse) slot
        }
        rs += fabsf(cs);
    }
    rs += __shfl_xor_sync(0xffffffffu, rs, 8);
    rs += __shfl_xor_sync(0xffffffffu, rs, 16);
    if (lane == 0) g_rowsum[row] = (rs > 0.f) ? 1.f / rs : 1.f;
}

// item-row reciprocal L1 rowsums from the already-written cos values (scalar reads)
__global__ __launch_bounds__(256) void k_rowsum_it() {
    int row = N_USER + blockIdx.x * 8 + (threadIdx.x >> 5);
    if (row >= NN) return;
    int lane = threadIdx.x & 31;
    int beg = g_rowptr[row], end = g_rowptr[row + 1];
    float rs = 0.f;
    for (int pos = beg + lane; pos < end; pos += 32)
        rs += fabsf(((const float*)(g_edge + pos))[1]);
    #pragma unroll
    for (int o = 16; o; o >>= 1) rs += __shfl_xor_sync(0xffffffffu, rs, o);
    if (lane == 0) g_rowsum[row] = (rs > 0.f) ? 1.f / rs : 1.f;
}

// coef -> prune -> mem EMA -> SpMM row accumulate (+ light sum, + next rnorm)
__global__ __launch_bounds__(256) void k_spmm(int cur, int last,
                                              const float* __restrict__ W,
                                              const float* __restrict__ B) {
    const float* __restrict__ embin = cur ? g_embB : g_embA;
    float* embout                   = cur ? g_embA : g_embB;
    int row = blockIdx.x * 8 + (threadIdx.x >> 5);
    if (row >= NN) return;
    int lane = threadIdx.x & 31;
    int g = lane >> 3, sl = lane & 7;

    float w0 = W[0], w1 = W[1], bb = B[0];
    float invr = g_rowsum[row];   // already reciprocal
    int beg = g_rowptr[row], end = g_rowptr[row + 1];
    int nit = (end - beg + 3) >> 2;

    // prefetch first edge record
    int pos = beg + g;
    bool actn = pos < end;
    float4 en = actn ? g_edge[pos] : make_float4(0, 0, 0, 0);

    float a0 = 0.f, a1 = 0.f, a2 = 0.f, a3 = 0.f;
    float a4 = 0.f, a5 = 0.f, a6 = 0.f, a7 = 0.f;
    for (int it = 0; it < nit; it++) {
        bool act = actn;
        float4 er = en;
        int curpos = pos;
        pos += 4;
        actn = pos < end;
        if (actn) en = g_edge[pos];       // prefetch next edge record

        if (act) {
            int c = __float_as_int(er.x);
            float cs = er.y;
            float c1 = cs * invr;
            float c2 = cs * g_rowsum[c];           // cos symmetric: coef[rev] = cs / rowsum[dst]
            float z = w0 * c1 + w1 * c2 + bb;      // sigmoid(z)>0.5 <=> z>0
            float coef = (z > 0.f) ? c1 : 0.f;
            float m = 0.5f * (er.z + coef);
            if (!last && sl == 0) ((float*)(g_edge + curpos))[2] = m;
            float gv = m * er.w;
            const float* cp = embin + c * D + sl * 4;
            float4 d0 = *(const float4*)(cp);
            float4 d1 = *(const float4*)(cp + 32);
            a0 += gv * d0.x; a1 += gv * d0.y; a2 += gv * d0.z; a3 += gv * d0.w;
            a4 += gv * d1.x; a5 += gv * d1.y; a6 += gv * d1.z; a7 += gv * d1.w;
        }
    }
    // combine the 4 groups (same dims live in lanes sl, sl+8, sl+16, sl+24)
    #pragma unroll
    for (int o = 8; o <= 16; o <<= 1) {
        a0 += __shfl_xor_sync(0xffffffffu, a0, o);
        a1 += __shfl_xor_sync(0xffffffffu, a1, o);
        a2 += __shfl_xor_sync(0xffffffffu, a2, o);
        a3 += __shfl_xor_sync(0xffffffffu, a3, o);
        a4 += __shfl_xor_sync(0xffffffffu, a4, o);
        a5 += __shfl_xor_sync(0xffffffffu, a5, o);
        a6 += __shfl_xor_sync(0xffffffffu, a6, o);
        a7 += __shfl_xor_sync(0xffffffffu, a7, o);
    }
    // lane sl (group 0) now holds full sums for dims [4sl,4sl+4) and [32+4sl,+4)
    if (g == 0) {
        float* lp = g_light + row * D + sl * 4;
        float4 l0 = *(float4*)(lp);
        float4 l1 = *(float4*)(lp + 32);
        l0.x += a0; l0.y += a1; l0.z += a2; l0.w += a3;
        l1.x += a4; l1.y += a5; l1.z += a6; l1.w += a7;
        *(float4*)(lp)      = l0;
        *(float4*)(lp + 32) = l1;
    }
    if (!last) {
        float ss = a0 * a0 + a1 * a1 + a2 * a2 + a3 * a3
                 + a4 * a4 + a5 * a5 + a6 * a6 + a7 * a7;
        ss += __shfl_xor_sync(0xffffffffu, ss, 1);
        ss += __shfl_xor_sync(0xffffffffu, ss, 2);
        ss += __shfl_xor_sync(0xffffffffu, ss, 4);
        if (g == 0) {
            float* op = embout + row * D + sl * 4;
            *(float4*)(op)      = make_float4(a0, a1, a2, a3);
            *(float4*)(op + 32) = make_float4(a4, a5, a6, a7);
            if (sl == 0) g_rnorm[row] = (ss > 1e-24f) ? rsqrtf(ss) : 0.f;
        }
    }
}

// ---------------- final: fused gather + sigmoid GEMM ----------------

__global__ void k_gemm(const int* __restrict__ users, const int* __restrict__ items,
                       float* __restrict__ out, int Bu, int Bi) {
    __shared__ float As[64][65];
    __shared__ float Bs[64][65];
    int tx = threadIdx.x, ty = threadIdx.y;       // 16x16
    int t = ty * 16 + tx;
    int rowBase = blockIdx.y * 64, colBase = blockIdx.x * 64;
    #pragma unroll
    for (int i = 0; i < 4; i++) {
        int j = t + i * 256;       // float4 slot 0..1023
        int r = j >> 4;
        int kq = (j & 15) * 4;
        float4 a = make_float4(0, 0, 0, 0);
        if (rowBase + r < Bu) {
            int u = users[rowBase + r];
            float4 v = *(const float4*)(g_light + u * D + kq);
            a = make_float4(0.25f * v.x, 0.25f * v.y, 0.25f * v.z, 0.25f * v.w);
        }
        As[r][kq] = a.x; As[r][kq + 1] = a.y; As[r][kq + 2] = a.z; As[r][kq + 3] = a.w;
        float4 b = make_float4(0, 0, 0, 0);
        if (colBase + r < Bi) {
            int itm = items[colBase + r];
            float4 v = *(const float4*)(g_light + (N_USER + itm) * D + kq);
            b = make_float4(0.25f * v.x, 0.25f * v.y, 0.25f * v.z, 0.25f * v.w);
        }
        Bs[r][kq] = b.x; Bs[r][kq + 1] = b.y; Bs[r][kq + 2] = b.z; Bs[r][kq + 3] = b.w;
    }
    __syncthreads();
    float acc[4][4] = {};
    #pragma unroll
    for (int k = 0; k < 64; k++) {
        float a0 = As[ty * 4 + 0][k], a1 = As[ty * 4 + 1][k];
        float a2 = As[ty * 4 + 2][k], a3 = As[ty * 4 + 3][k];
        float b0 = Bs[tx * 4 + 0][k], b1 = Bs[tx * 4 + 1][k];
        float b2 = Bs[tx * 4 + 2][k], b3 = Bs[tx * 4 + 3][k];
        acc[0][0] += a0 * b0; acc[0][1] += a0 * b1; acc[0][2] += a0 * b2; acc[0][3] += a0 * b3;
        acc[1][0] += a1 * b0; acc[1][1] += a1 * b1; acc[1][2] += a1 * b2; acc[1][3] += a1 * b3;
        acc[2][0] += a2 * b0; acc[2][1] += a2 * b1; acc[2][2] += a2 * b2; acc[2][3] += a2 * b3;
        acc[3][0] += a3 * b0; acc[3][1] += a3 * b1; acc[3][2] += a3 * b2; acc[3][3] += a3 * b3;
    }
    #pragma unroll
    for (int i = 0; i < 4; i++)
        #pragma unroll
        for (int j = 0; j < 4; j++) {
            int r = rowBase + ty * 4 + i;
            int c = colBase + tx * 4 + j;
            if (r < Bu && c < Bi)
                out[r * Bi + c] = 1.f / (1.f + __expf(-acc[i][j]));
        }
}

// ---------------- launch ----------------

extern "C" void kernel_launch(void* const* d_in, const int* in_sizes, int n_in,
                              void* d_out, int out_size) {
    const int*   users    = (const int*)d_in[0];
    const int*   items    = (const int*)d_in[1];
    const float* user_emb = (const float*)d_in[2];
    const float* item_emb = (const float*)d_in[3];
    const float* W_prune  = (const float*)d_in[4];
    const float* b_prune  = (const float*)d_in[5];
    const int*   src      = (const int*)d_in[6];
    // d_in[7] = dst (mirrors src), d_in[8] = rev_perm (unused)
    const float* adj_vals = (const float*)d_in[9];

    int Bu = in_sizes[0];
    int Bi = in_sizes[1];
    int E  = in_sizes[6];
    int EH = E / 2;

    float* out = (float*)d_out;

    // zero degree counters
    void* degp = nullptr;
    cudaGetSymbolAddress(&degp, g_deg);
    cudaMemsetAsync(degp, 0, NN * sizeof(int));

    // CSR build
    k_hist<<<(E + 1023) / 1024, 1024>>>(src, E);
    k_scanA<<<NB_SCAN, 1024>>>();
    k_scanB<<<1, 128>>>(NB_SCAN);
    k_scanC<<<NB_SCAN, 1024>>>(E);
    k_scatter<<<(EH + 1023) / 1024, 1024>>>(src, adj_vals, EH);

    // init embeddings + light + layer-0 reciprocal norms
    k_init<<<(NN + 7) / 8, 256>>>(user_emb, item_emb);

    // 3 propagation layers
    int ublocks = (N_USER + 7) / 8;
    int iblocks = (N_ITEM + 7) / 8;
    int ablocks = (NN + 7) / 8;
    for (int l = 0; l < 3; l++) {
        int cur = l & 1;
        k_cos<<<ublocks, 256>>>(cur);
        k_rowsum_it<<<iblocks, 256>>>();
        k_spmm<<<ablocks, 256>>>(cur, l == 2, W_prune, b_prune);
    }

    // fused gather + sigmoid GEMM
    dim3 gblk(16, 16);
    dim3 ggrd((Bi + 63) / 64, (Bu + 63) / 64);
    k_gemm<<<ggrd, gblk>>>(users, items, out, Bu, Bi);
}